// round 4
// baseline (speedup 1.0000x reference)
#include <cuda_runtime.h>
#include <math.h>

#define NQ 256
#define ND 256
#define NI 2048
#define SE_INV_TEMP 5.0f
#define BN_EPS 1e-5f

// ---- scratch (no allocations allowed) ----
__device__ float g_A1[NQ * ND];   // u_hat * w
__device__ float g_A2[NQ * ND];   // w * w
__device__ float g_A3[NQ * ND];   // 2 * w * b
__device__ float g_c1[NQ];        // u_hat . b
__device__ float g_B;             // sum b^2
__device__ float g_yg[NI * ND];   // l2-normalized gallery

// ---- packed f32x2 ops (Blackwell FFMA2 path, only reachable via PTX) ----
#define FMA2(d, a, b) \
    asm("fma.rn.f32x2 %0, %1, %2, %0;" : "+l"(d) : "l"(a), "l"(b))
#define MUL2(d, a, b) \
    asm("mul.rn.f32x2 %0, %1, %2;" : "=l"(d) : "l"(a), "l"(b))

__device__ __forceinline__ float lo32(unsigned long long v) {
    return __uint_as_float((unsigned)(v & 0xffffffffull));
}
__device__ __forceinline__ float hi32(unsigned long long v) {
    return __uint_as_float((unsigned)(v >> 32));
}

__device__ __forceinline__ float warpSum(float v) {
#pragma unroll
    for (int o = 16; o > 0; o >>= 1) v += __shfl_xor_sync(0xffffffffu, v, o);
    return v;
}

// ---- Kernel A: warp-per-row gallery normalize (8 floats/lane) ----
__global__ __launch_bounds__(256) void gallery_prep(const float* __restrict__ gal) {
    int w = threadIdx.x >> 5, lane = threadIdx.x & 31;
    int i = blockIdx.x * 8 + w;
    const float4* src = (const float4*)(gal + i * ND);
    float4 a = src[lane * 2];
    float4 b = src[lane * 2 + 1];
    float ss = a.x * a.x + a.y * a.y + a.z * a.z + a.w * a.w +
               b.x * b.x + b.y * b.y + b.z * b.z + b.w * b.w;
    ss = warpSum(ss);
    float r = 1.f / fmaxf(sqrtf(ss), 1e-12f);
    a.x *= r; a.y *= r; a.z *= r; a.w *= r;
    b.x *= r; b.y *= r; b.z *= r; b.w *= r;
    float4* dst = (float4*)(g_yg + i * ND);
    dst[lane * 2] = a;
    dst[lane * 2 + 1] = b;
}

// ---- Kernel B: warp-per-row query precompute (8 floats/lane) ----
__global__ __launch_bounds__(256) void query_prep(
    const float* __restrict__ qf, const float* __restrict__ qif,
    const float* __restrict__ gamma, const float* __restrict__ beta,
    const float* __restrict__ mean, const float* __restrict__ var) {
    int w = threadIdx.x >> 5, lane = threadIdx.x & 31;
    int q = blockIdx.x * 8 + w;
    int d0 = lane * 8;

    float gm[8], bt[8], mn[8], vr[8], x[8], y[8];
    *(float4*)&gm[0] = *(const float4*)(gamma + d0);
    *(float4*)&gm[4] = *(const float4*)(gamma + d0 + 4);
    *(float4*)&bt[0] = *(const float4*)(beta + d0);
    *(float4*)&bt[4] = *(const float4*)(beta + d0 + 4);
    *(float4*)&mn[0] = *(const float4*)(mean + d0);
    *(float4*)&mn[4] = *(const float4*)(mean + d0 + 4);
    *(float4*)&vr[0] = *(const float4*)(var + d0);
    *(float4*)&vr[4] = *(const float4*)(var + d0 + 4);
    *(float4*)&x[0] = *(const float4*)(qf + q * ND + d0);
    *(float4*)&x[4] = *(const float4*)(qf + q * ND + d0 + 4);
    *(float4*)&y[0] = *(const float4*)(qif + q * ND + d0);
    *(float4*)&y[4] = *(const float4*)(qif + q * ND + d0 + 4);

    float s[8], bb[8];
    float nx = 0.f, ny = 0.f;
#pragma unroll
    for (int j = 0; j < 8; ++j) {
        s[j] = gm[j] * rsqrtf(vr[j] + BN_EPS);
        bb[j] = bt[j] - mn[j] * s[j];
        nx += x[j] * x[j];
        ny += y[j] * y[j];
    }
    nx = warpSum(nx);
    ny = warpSum(ny);
    float rx = 1.f / fmaxf(sqrtf(nx), 1e-12f);
    float ry = 1.f / fmaxf(sqrtf(ny), 1e-12f);

    float ww[8], u[8];
    float nu = 0.f;
#pragma unroll
    for (int j = 0; j < 8; ++j) {
        float xh = x[j] * rx;
        float gate = 1.f / (1.f + __expf(-xh * SE_INV_TEMP));
        ww[j] = gate * s[j];
        u[j] = y[j] * ry * ww[j] + bb[j];
        nu += u[j] * u[j];
    }
    nu = warpSum(nu);
    float ru = 1.f / fmaxf(sqrtf(nu), 1e-12f);

    float a1[8], a2[8], a3[8];
    float c1 = 0.f, Bacc = 0.f;
#pragma unroll
    for (int j = 0; j < 8; ++j) {
        float uh = u[j] * ru;
        a1[j] = uh * ww[j];
        a2[j] = ww[j] * ww[j];
        a3[j] = 2.f * ww[j] * bb[j];
        c1 += uh * bb[j];
        Bacc += bb[j] * bb[j];
    }
    *(float4*)(g_A1 + q * ND + d0) = *(float4*)&a1[0];
    *(float4*)(g_A1 + q * ND + d0 + 4) = *(float4*)&a1[4];
    *(float4*)(g_A2 + q * ND + d0) = *(float4*)&a2[0];
    *(float4*)(g_A2 + q * ND + d0 + 4) = *(float4*)&a2[4];
    *(float4*)(g_A3 + q * ND + d0) = *(float4*)&a3[0];
    *(float4*)(g_A3 + q * ND + d0 + 4) = *(float4*)&a3[4];

    c1 = warpSum(c1);
    if (lane == 0) g_c1[q] = c1;
    if (q == 0) {
        Bacc = warpSum(Bacc);
        if (lane == 0) g_B = Bacc;
    }
}

// ---- Kernel C: fused triple GEMM + sigmoid, f32x2 packed, double-buffered ----
// scores[q,i] = sigmoid((yg.A1 + c1) * rsqrt(yg^2.A2 + yg.A3 + B))
#define TI 64
#define TQ 64
#define KC 32
#define LDA 68    // stride of sYG (i-major per k)
#define LDB 132   // stride of duplicated q-side arrays (2 floats per q value)
#define SZ_A (KC * LDA)   // 2176 floats
#define SZ_B (KC * LDB)   // 4224 floats
#define SMEM_FLOATS (2 * SZ_A + 6 * SZ_B)
#define SMEM_BYTES (SMEM_FLOATS * 4)

__global__ __launch_bounds__(256) void score_main(float* __restrict__ out) {
    extern __shared__ float sm[];
    float* sYG = sm;                       // [2][SZ_A]
    float* sB1 = sm + 2 * SZ_A;            // [2][SZ_B] (A1 duplicated)
    float* sB2 = sB1 + 2 * SZ_B;           // [2][SZ_B] (A2 duplicated)
    float* sB3 = sB2 + 2 * SZ_B;           // [2][SZ_B] (A3 duplicated)

    const int iBase = blockIdx.x * TI;
    const int qBase = blockIdx.y * TQ;
    const int tid = threadIdx.x;

    // staging: 32 rows x 8 k-quads per pass, 2 passes
    const int sr = tid >> 3;
    const int skq = (tid & 7) * 4;

    // compute: 16x16 threads, 4x4 micro-tile (i packed in f32x2 pairs)
    const int i0 = (tid & 15) * 4;
    const int q0 = (tid >> 4) * 4;

    float4 rg[2], r1[2], r2[2], r3[2];

    auto FETCH = [&](int k0) {
#pragma unroll
        for (int p = 0; p < 2; ++p) {
            int row = sr + p * 32;
            rg[p] = *(const float4*)&g_yg[(iBase + row) * ND + k0 + skq];
            r1[p] = *(const float4*)&g_A1[(qBase + row) * ND + k0 + skq];
            r2[p] = *(const float4*)&g_A2[(qBase + row) * ND + k0 + skq];
            r3[p] = *(const float4*)&g_A3[(qBase + row) * ND + k0 + skq];
        }
    };
    auto STORE = [&](int buf) {
        float* yg = sYG + buf * SZ_A;
        float* b1 = sB1 + buf * SZ_B;
        float* b2 = sB2 + buf * SZ_B;
        float* b3 = sB3 + buf * SZ_B;
#pragma unroll
        for (int p = 0; p < 2; ++p) {
            int row = sr + p * 32;
            const float* pg = &rg[p].x;
            const float* p1 = &r1[p].x;
            const float* p2 = &r2[p].x;
            const float* p3 = &r3[p].x;
#pragma unroll
            for (int j = 0; j < 4; ++j) {
                yg[(skq + j) * LDA + row] = pg[j];
                *(float2*)&b1[(skq + j) * LDB + 2 * row] = make_float2(p1[j], p1[j]);
                *(float2*)&b2[(skq + j) * LDB + 2 * row] = make_float2(p2[j], p2[j]);
                *(float2*)&b3[(skq + j) * LDB + 2 * row] = make_float2(p3[j], p3[j]);
            }
        }
    };

    unsigned long long aN[2][4], aD[2][4];
#pragma unroll
    for (int p = 0; p < 2; ++p)
#pragma unroll
        for (int qq = 0; qq < 4; ++qq) { aN[p][qq] = 0ull; aD[p][qq] = 0ull; }

    FETCH(0);
    STORE(0);

    for (int t = 0; t < ND / KC; ++t) {
        __syncthreads();
        if (t < ND / KC - 1) FETCH((t + 1) * KC);

        const float* yg = sYG + (t & 1) * SZ_A;
        const float* b1 = sB1 + (t & 1) * SZ_B;
        const float* b2 = sB2 + (t & 1) * SZ_B;
        const float* b3 = sB3 + (t & 1) * SZ_B;

#pragma unroll 8
        for (int k = 0; k < KC; ++k) {
            ulonglong2 ag = *(const ulonglong2*)&yg[k * LDA + i0];
            ulonglong2 c1a = *(const ulonglong2*)&b1[k * LDB + q0 * 2];
            ulonglong2 c1b = *(const ulonglong2*)&b1[k * LDB + q0 * 2 + 4];
            ulonglong2 c2a = *(const ulonglong2*)&b2[k * LDB + q0 * 2];
            ulonglong2 c2b = *(const ulonglong2*)&b2[k * LDB + q0 * 2 + 4];
            ulonglong2 c3a = *(const ulonglong2*)&b3[k * LDB + q0 * 2];
            ulonglong2 c3b = *(const ulonglong2*)&b3[k * LDB + q0 * 2 + 4];

            unsigned long long ag2x, ag2y;
            MUL2(ag2x, ag.x, ag.x);
            MUL2(ag2y, ag.y, ag.y);

            FMA2(aN[0][0], ag.x, c1a.x);  FMA2(aN[1][0], ag.y, c1a.x);
            FMA2(aN[0][1], ag.x, c1a.y);  FMA2(aN[1][1], ag.y, c1a.y);
            FMA2(aN[0][2], ag.x, c1b.x);  FMA2(aN[1][2], ag.y, c1b.x);
            FMA2(aN[0][3], ag.x, c1b.y);  FMA2(aN[1][3], ag.y, c1b.y);

            FMA2(aD[0][0], ag2x, c2a.x);  FMA2(aD[1][0], ag2y, c2a.x);
            FMA2(aD[0][1], ag2x, c2a.y);  FMA2(aD[1][1], ag2y, c2a.y);
            FMA2(aD[0][2], ag2x, c2b.x);  FMA2(aD[1][2], ag2y, c2b.x);
            FMA2(aD[0][3], ag2x, c2b.y);  FMA2(aD[1][3], ag2y, c2b.y);

            FMA2(aD[0][0], ag.x, c3a.x);  FMA2(aD[1][0], ag.y, c3a.x);
            FMA2(aD[0][1], ag.x, c3a.y);  FMA2(aD[1][1], ag.y, c3a.y);
            FMA2(aD[0][2], ag.x, c3b.x);  FMA2(aD[1][2], ag.y, c3b.x);
            FMA2(aD[0][3], ag.x, c3b.y);  FMA2(aD[1][3], ag.y, c3b.y);
        }

        if (t < ND / KC - 1) STORE((t + 1) & 1);
    }

    float Bv = g_B;
#pragma unroll
    for (int qq = 0; qq < 4; ++qq) {
        int qg = qBase + q0 + qq;
        float c1v = g_c1[qg];
        float4 res;
        float n0 = lo32(aN[0][qq]) + c1v;
        float n1 = hi32(aN[0][qq]) + c1v;
        float n2 = lo32(aN[1][qq]) + c1v;
        float n3 = hi32(aN[1][qq]) + c1v;
        float d0 = lo32(aD[0][qq]) + Bv;
        float d1 = hi32(aD[0][qq]) + Bv;
        float d2 = lo32(aD[1][qq]) + Bv;
        float d3 = hi32(aD[1][qq]) + Bv;
        float s0 = n0 * rsqrtf(fmaxf(d0, 1e-24f));
        float s1 = n1 * rsqrtf(fmaxf(d1, 1e-24f));
        float s2 = n2 * rsqrtf(fmaxf(d2, 1e-24f));
        float s3 = n3 * rsqrtf(fmaxf(d3, 1e-24f));
        res.x = 1.f / (1.f + __expf(-s0));
        res.y = 1.f / (1.f + __expf(-s1));
        res.z = 1.f / (1.f + __expf(-s2));
        res.w = 1.f / (1.f + __expf(-s3));
        *(float4*)&out[qg * NI + iBase + i0] = res;
    }
}

extern "C" void kernel_launch(void* const* d_in, const int* in_sizes, int n_in,
                              void* d_out, int out_size) {
    const float* query_feats = (const float*)d_in[0];
    const float* query_img_feats = (const float*)d_in[1];
    const float* gallery_img_feats = (const float*)d_in[2];
    const float* bn_gamma = (const float*)d_in[3];
    const float* bn_beta = (const float*)d_in[4];
    const float* bn_mean = (const float*)d_in[5];
    const float* bn_var = (const float*)d_in[6];
    float* out = (float*)d_out;

    // >48KB dynamic smem opt-in (idempotent; takes effect on first
    // non-captured correctness call, sticky per-function thereafter).
    cudaFuncSetAttribute(score_main, cudaFuncAttributeMaxDynamicSharedMemorySize,
                         SMEM_BYTES);

    gallery_prep<<<NI / 8, 256>>>(gallery_img_feats);
    query_prep<<<NQ / 8, 256>>>(query_feats, query_img_feats, bn_gamma, bn_beta,
                                bn_mean, bn_var);
    dim3 grid(NI / TI, NQ / TQ);
    score_main<<<grid, 256, SMEM_BYTES>>>(out);
}

// round 12
// speedup vs baseline: 1.6237x; 1.6237x over previous
#include <cuda_runtime.h>
#include <cuda_bf16.h>
#include <cstdint>
#include <math.h>

#define NQ 256
#define ND 256
#define NI 2048
#define KTOT 512          // concat K: [yg | yg^2]
#define SE_INV_TEMP 5.0f
#define BN_EPS 1e-5f

// GEMM tile config
#define TM 128            // M tile (gallery i)
#define TN 64             // N tile (2 cols per query: num, den) -> 32 q per block
#define KC 128            // K per chunk (128 bf16 = 256 BYTES per row)
#define NCHUNK (KTOT / KC)      // 4 per pass
#define NPASS 3                 // Ah*Bh, Ah*Bl, Al*Bh
#define NCHTOT (NPASS * NCHUNK) // 12
#define LDAB 136          // smem row stride in bf16 (128 + 8 pad = 272 bytes)
#define A_STAGE_B (TM * LDAB * 2)            // 34816
#define B_STAGE_B (TN * LDAB * 2)            // 17408
#define STAGE_B (A_STAGE_B + B_STAGE_B)      // 52224
#define SMEM_BYTES (2 * STAGE_B)             // 104448
#define LDS_SC 132        // float stride for score transpose

// ---- device scratch (no allocs allowed) ----
__device__ __nv_bfloat16 g_Ahi[NI * KTOT];     // [i][yg(256) | yg^2(256)] hi
__device__ __nv_bfloat16 g_Alo[NI * KTOT];     // lo residual
__device__ __nv_bfloat16 g_Bhi[2 * NQ * KTOT]; // row 2q=[A1|0], 2q+1=[A3|A2] hi
__device__ __nv_bfloat16 g_Blo[2 * NQ * KTOT]; // lo residual
__device__ float g_c1[NQ];
__device__ float g_B;

__device__ __forceinline__ uint32_t smem_to_u32(const void* p) {
    uint32_t a;
    asm("{ .reg .u64 t; cvta.to.shared.u64 t, %1; cvt.u32.u64 %0, t; }"
        : "=r"(a) : "l"(p));
    return a;
}

__device__ __forceinline__ float warpSum(float v) {
#pragma unroll
    for (int o = 16; o > 0; o >>= 1) v += __shfl_xor_sync(0xffffffffu, v, o);
    return v;
}
__device__ __forceinline__ uint32_t pk2(float a, float b) {
    __nv_bfloat162 h = __floats2bfloat162_rn(a, b);
    return *reinterpret_cast<uint32_t*>(&h);
}
__device__ __forceinline__ void st8bf(__nv_bfloat16* p, const float* v) {
    uint4 u;
    u.x = pk2(v[0], v[1]); u.y = pk2(v[2], v[3]);
    u.z = pk2(v[4], v[5]); u.w = pk2(v[6], v[7]);
    *reinterpret_cast<uint4*>(p) = u;
}
// store hi/lo split of 8 floats
__device__ __forceinline__ void st8split(__nv_bfloat16* phi, __nv_bfloat16* plo,
                                         const float* v) {
    float hi[8], lo[8];
#pragma unroll
    for (int j = 0; j < 8; ++j) {
        __nv_bfloat16 h = __float2bfloat16(v[j]);
        hi[j] = __bfloat162float(h);
        lo[j] = v[j] - hi[j];
    }
    st8bf(phi, hi);
    st8bf(plo, lo);
}

// ---- fused prep: blocks [0,256) gallery rows, [256,288) query rows ----
__global__ __launch_bounds__(256) void prep(
    const float* __restrict__ qf, const float* __restrict__ qif,
    const float* __restrict__ gal,
    const float* __restrict__ gamma, const float* __restrict__ beta,
    const float* __restrict__ mean, const float* __restrict__ var) {
    int w = threadIdx.x >> 5, lane = threadIdx.x & 31;
    int d0 = lane * 8;

    if (blockIdx.x < 256) {
        int i = blockIdx.x * 8 + w;
        float v[8];
        *(float4*)&v[0] = *(const float4*)(gal + i * ND + d0);
        *(float4*)&v[4] = *(const float4*)(gal + i * ND + d0 + 4);
        float ss = 0.f;
#pragma unroll
        for (int j = 0; j < 8; ++j) ss += v[j] * v[j];
        ss = warpSum(ss);
        float r = 1.f / fmaxf(sqrtf(ss), 1e-12f);
        float yg[8], yg2[8];
#pragma unroll
        for (int j = 0; j < 8; ++j) { yg[j] = v[j] * r; yg2[j] = yg[j] * yg[j]; }
        st8split(g_Ahi + i * KTOT + d0, g_Alo + i * KTOT + d0, yg);
        st8split(g_Ahi + i * KTOT + ND + d0, g_Alo + i * KTOT + ND + d0, yg2);
    } else {
        int q = (blockIdx.x - 256) * 8 + w;
        float gm[8], bt[8], mn[8], vr[8], x[8], y[8];
        *(float4*)&gm[0] = *(const float4*)(gamma + d0);
        *(float4*)&gm[4] = *(const float4*)(gamma + d0 + 4);
        *(float4*)&bt[0] = *(const float4*)(beta + d0);
        *(float4*)&bt[4] = *(const float4*)(beta + d0 + 4);
        *(float4*)&mn[0] = *(const float4*)(mean + d0);
        *(float4*)&mn[4] = *(const float4*)(mean + d0 + 4);
        *(float4*)&vr[0] = *(const float4*)(var + d0);
        *(float4*)&vr[4] = *(const float4*)(var + d0 + 4);
        *(float4*)&x[0] = *(const float4*)(qf + q * ND + d0);
        *(float4*)&x[4] = *(const float4*)(qf + q * ND + d0 + 4);
        *(float4*)&y[0] = *(const float4*)(qif + q * ND + d0);
        *(float4*)&y[4] = *(const float4*)(qif + q * ND + d0 + 4);

        float s[8], bb[8];
        float nx = 0.f, ny = 0.f;
#pragma unroll
        for (int j = 0; j < 8; ++j) {
            s[j] = gm[j] * rsqrtf(vr[j] + BN_EPS);
            bb[j] = bt[j] - mn[j] * s[j];
            nx += x[j] * x[j];
            ny += y[j] * y[j];
        }
        nx = warpSum(nx); ny = warpSum(ny);
        float rx = 1.f / fmaxf(sqrtf(nx), 1e-12f);
        float ry = 1.f / fmaxf(sqrtf(ny), 1e-12f);

        float ww[8], u[8];
        float nu = 0.f;
#pragma unroll
        for (int j = 0; j < 8; ++j) {
            float xh = x[j] * rx;
            float gate = 1.f / (1.f + __expf(-xh * SE_INV_TEMP));
            ww[j] = gate * s[j];
            u[j] = y[j] * ry * ww[j] + bb[j];
            nu += u[j] * u[j];
        }
        nu = warpSum(nu);
        float ru = 1.f / fmaxf(sqrtf(nu), 1e-12f);

        float a1[8], a2[8], a3[8], zz[8];
        float c1 = 0.f, Bacc = 0.f;
#pragma unroll
        for (int j = 0; j < 8; ++j) {
            float uh = u[j] * ru;
            a1[j] = uh * ww[j];
            a2[j] = ww[j] * ww[j];
            a3[j] = 2.f * ww[j] * bb[j];
            zz[j] = 0.f;
            c1 += uh * bb[j];
            Bacc += bb[j] * bb[j];
        }
        int r0 = (2 * q) * KTOT, r1 = (2 * q + 1) * KTOT;
        st8split(g_Bhi + r0 + d0, g_Blo + r0 + d0, a1);
        st8bf(g_Bhi + r0 + ND + d0, zz);
        st8bf(g_Blo + r0 + ND + d0, zz);
        st8split(g_Bhi + r1 + d0, g_Blo + r1 + d0, a3);
        st8split(g_Bhi + r1 + ND + d0, g_Blo + r1 + ND + d0, a2);

        c1 = warpSum(c1);
        if (lane == 0) g_c1[q] = c1;
        if (q == 0) {
            Bacc = warpSum(Bacc);
            if (lane == 0) g_B = Bacc;
        }
    }
}

// ================= bf16 mma.sync GEMM (split-bf16 x3) + fused epilogue ======
// D = Ah*Bh + Ah*Bl + Al*Bh ; out[q,i] = sigmoid((D[i,2q]+c1)*rsqrt(D[i,2q+1]+B))
__global__ __launch_bounds__(256, 1) void score_mma(float* __restrict__ out) {
    extern __shared__ char smem[];
    const uint32_t smem_u = smem_to_u32(smem);
    const int tid = threadIdx.x;
    const int wid = tid >> 5, lane = tid & 31;
    const int wm = wid >> 1;        // 0..3 -> 32-row band
    const int wn = wid & 1;         // 0..1 -> 32-col band
    const int iBase = blockIdx.x * TM;
    const int nBase = blockIdx.y * TN;
    const int qBase = nBase >> 1;   // 32 q per block

    float c[2][4][4];
#pragma unroll
    for (int a = 0; a < 2; ++a)
#pragma unroll
        for (int b = 0; b < 4; ++b)
#pragma unroll
            for (int e = 0; e < 4; ++e) c[a][b][e] = 0.f;

    // per-thread ldmatrix base offsets (byte offsets within a stage)
    const int lmRow = lane & 15;
    const int lmColB = ((lane >> 4) & 1) * 16;
    uint32_t aOffs[2], bOffs[2];
#pragma unroll
    for (int mt = 0; mt < 2; ++mt)
        aOffs[mt] = (uint32_t)((wm * 32 + mt * 16 + lmRow) * (LDAB * 2) + lmColB);
#pragma unroll
    for (int g = 0; g < 2; ++g)
        bOffs[g] = (uint32_t)(A_STAGE_B + (wn * 32 + g * 16 + lmRow) * (LDAB * 2) + lmColB);

    // FIXED STAGING (R12): full 256B per A row (16 x 16B chunks), full B tile.
    // A: 128 rows x 16 chunks = 2048 chunks -> fa[8]; B: 64 x 16 = 1024 -> fb[4].
    uint4 fa[8], fb[4];
    auto FETCH = [&](int u) {
        const int p = u >> 2;        // pass: 0=Ah*Bh 1=Ah*Bl 2=Al*Bh
        const int t = u & 3;         // k chunk within pass
        const __nv_bfloat16* As = (p == 2) ? g_Alo : g_Ahi;
        const __nv_bfloat16* Bs = (p == 1) ? g_Blo : g_Bhi;
#pragma unroll
        for (int j = 0; j < 8; ++j) {
            int cidx = tid + j * 256;            // [0, 2048)
            int row = cidx >> 4, c16 = cidx & 15;
            fa[j] = *(const uint4*)(As + (iBase + row) * KTOT + t * KC + c16 * 8);
        }
#pragma unroll
        for (int j = 0; j < 4; ++j) {
            int cidx = tid + j * 256;            // [0, 1024)
            int row = cidx >> 4, c16 = cidx & 15;
            fb[j] = *(const uint4*)(Bs + (nBase + row) * KTOT + t * KC + c16 * 8);
        }
    };
    auto STORE = [&](int buf) {
        char* sA = smem + buf * STAGE_B;
        char* sB = sA + A_STAGE_B;
#pragma unroll
        for (int j = 0; j < 8; ++j) {
            int cidx = tid + j * 256;
            int row = cidx >> 4, c16 = cidx & 15;
            *(uint4*)(sA + row * (LDAB * 2) + c16 * 16) = fa[j];
        }
#pragma unroll
        for (int j = 0; j < 4; ++j) {
            int cidx = tid + j * 256;
            int row = cidx >> 4, c16 = cidx & 15;
            *(uint4*)(sB + row * (LDAB * 2) + c16 * 16) = fb[j];
        }
    };

    FETCH(0);
    STORE(0);

    for (int u = 0; u < NCHTOT; ++u) {
        __syncthreads();
        if (u < NCHTOT - 1) FETCH(u + 1);

        const uint32_t stage = smem_u + (u & 1) * STAGE_B;
#pragma unroll
        for (int kk = 0; kk < KC / 16; ++kk) {
            uint32_t a0[2], a1[2], a2[2], a3[2];
#pragma unroll
            for (int mt = 0; mt < 2; ++mt) {
                uint32_t addr = stage + aOffs[mt] + kk * 32;
                asm volatile(
                    "ldmatrix.sync.aligned.m8n8.x4.shared.b16 {%0,%1,%2,%3}, [%4];"
                    : "=r"(a0[mt]), "=r"(a1[mt]), "=r"(a2[mt]), "=r"(a3[mt])
                    : "r"(addr));
            }
            uint32_t b0[4], b1[4];
#pragma unroll
            for (int g = 0; g < 2; ++g) {
                uint32_t addr = stage + bOffs[g] + kk * 32;
                uint32_t r0, r1, r2, r3;
                asm volatile(
                    "ldmatrix.sync.aligned.m8n8.x4.shared.b16 {%0,%1,%2,%3}, [%4];"
                    : "=r"(r0), "=r"(r1), "=r"(r2), "=r"(r3)
                    : "r"(addr));
                b0[g * 2] = r0; b0[g * 2 + 1] = r1;
                b1[g * 2] = r2; b1[g * 2 + 1] = r3;
            }
#pragma unroll
            for (int mt = 0; mt < 2; ++mt)
#pragma unroll
                for (int nt = 0; nt < 4; ++nt) {
                    asm volatile(
                        "mma.sync.aligned.m16n8k16.row.col.f32.bf16.bf16.f32 "
                        "{%0,%1,%2,%3}, {%4,%5,%6,%7}, {%8,%9}, {%0,%1,%2,%3};"
                        : "+f"(c[mt][nt][0]), "+f"(c[mt][nt][1]),
                          "+f"(c[mt][nt][2]), "+f"(c[mt][nt][3])
                        : "r"(a0[mt]), "r"(a1[mt]), "r"(a2[mt]), "r"(a3[mt]),
                          "r"(b0[nt]), "r"(b1[nt]));
                }
        }

        if (u < NCHTOT - 1) STORE((u + 1) & 1);
    }

    // ---- epilogue: register-local score, smem transpose, coalesced store ----
    float* sc = (float*)smem;  // 32 q x 128 i, stride LDS_SC (in stage-0 area)
    const float Bv = g_B;
#pragma unroll
    for (int nt = 0; nt < 4; ++nt) {
        int q_local = wn * 16 + nt * 4 + (lane & 3);
        float c1v = g_c1[qBase + q_local];
#pragma unroll
        for (int mt = 0; mt < 2; ++mt) {
            int r0 = wm * 32 + mt * 16 + (lane >> 2);
            float num0 = c[mt][nt][0] + c1v;
            float den0 = c[mt][nt][1] + Bv;
            float num1 = c[mt][nt][2] + c1v;
            float den1 = c[mt][nt][3] + Bv;
            float s0 = num0 * rsqrtf(fmaxf(den0, 1e-24f));
            float s1 = num1 * rsqrtf(fmaxf(den1, 1e-24f));
            sc[q_local * LDS_SC + r0] = 1.f / (1.f + __expf(-s0));
            sc[q_local * LDS_SC + r0 + 8] = 1.f / (1.f + __expf(-s1));
        }
    }
    __syncthreads();

    {
        int q_local = tid >> 3;
        int i0 = (tid & 7) * 16;
        float* dst = out + (qBase + q_local) * NI + iBase + i0;
        const float* src = sc + q_local * LDS_SC + i0;
#pragma unroll
        for (int j = 0; j < 4; ++j)
            *(float4*)(dst + j * 4) = *(const float4*)(src + j * 4);
    }
}

extern "C" void kernel_launch(void* const* d_in, const int* in_sizes, int n_in,
                              void* d_out, int out_size) {
    const float* query_feats = (const float*)d_in[0];
    const float* query_img_feats = (const float*)d_in[1];
    const float* gallery_img_feats = (const float*)d_in[2];
    const float* bn_gamma = (const float*)d_in[3];
    const float* bn_beta = (const float*)d_in[4];
    const float* bn_mean = (const float*)d_in[5];
    const float* bn_var = (const float*)d_in[6];
    float* out = (float*)d_out;

    cudaFuncSetAttribute(score_mma, cudaFuncAttributeMaxDynamicSharedMemorySize,
                         SMEM_BYTES);

    prep<<<288, 256>>>(query_feats, query_img_feats, gallery_img_feats,
                       bn_gamma, bn_beta, bn_mean, bn_var);
    dim3 grid(NI / TM, (2 * NQ) / TN);
    score_mma<<<grid, 256, SMEM_BYTES>>>(out);
}